// round 16
// baseline (speedup 1.0000x reference)
#include <cuda_runtime.h>
#include <cuda_bf16.h>
#include <math.h>

#define T_ 128
#define N_ 256
#define L_ 256
#define H_ 256
#define COND_ 64
#define ROWS_ (T_ * N_)   // 32768
#define OUTW_ 770

typedef unsigned long long u64;
typedef unsigned u32;

// ---------------- scratch (float units) --------------------------------------
#define XINH_OFF 0L                               // [ROWS][320] bf16
#define XINL_OFF (XINH_OFF + (long)ROWS_ * 160)
#define XAH_OFF  (XINL_OFF + (long)ROWS_ * 160)   // [ROWS][256] bf16
#define XAL_OFF  (XAH_OFF + (long)ROWS_ * 128)
#define XBH_OFF  (XAL_OFF + (long)ROWS_ * 128)
#define XBL_OFF  (XBH_OFF + (long)ROWS_ * 128)
#define GI_OFF   (XBL_OFF + (long)ROWS_ * 128)    // fp32 [ROWS][768]
#define KBH_OFF  (GI_OFF + (long)ROWS_ * 768)
#define KBL_OFF  (KBH_OFF + (long)ROWS_ * 128)
#define WB_OFF   (KBL_OFF + (long)ROWS_ * 128)    // fp32 [N][T][L]
#define CC_OFF   (WB_OFF + (long)ROWS_ * 256)
#define WT_OFF   (CC_OFF + (long)ROWS_)
#define WT_FLOATS 475136L
#define HBH_OFF  (WT_OFF + WT_FLOATS)
#define HBL_OFF  (HBH_OFF + 4194304L)
#define HB0H_OFF (HBL_OFF + 4194304L)
#define HB0L_OFF (HB0H_OFF + 32768L)
#define SCRATCH_FLOATS (HB0L_OFF + 32768L)

__device__ float g_scratch[SCRATCH_FLOATS];
__device__ unsigned g_bar2[8 * 32];   // per-nt arrive counters (monotonic)

// bf16 weight-buffer offsets (bf16 element units inside WT)
#define W0H 0
#define W0L 81920
#define W1H 163840
#define W1L 229376
#define W2H 294912
#define W2L 360448
#define WIHH 425984
#define WIHL 622592
#define WAH 819200
#define WAL 884736

// ---------------- bf16 helpers ------------------------------------------------
__device__ __forceinline__ void cvt_split(float x0, float x1, u32& h, u32& l) {
    u32 hh;
    asm("cvt.rn.bf16x2.f32 %0, %1, %2;" : "=r"(hh) : "f"(x1), "f"(x0));
    float r0 = x0 - __uint_as_float(hh << 16);
    float r1 = x1 - __uint_as_float(hh & 0xFFFF0000u);
    u32 ll;
    asm("cvt.rn.bf16x2.f32 %0, %1, %2;" : "=r"(ll) : "f"(r1), "f"(r0));
    h = hh; l = ll;
}
__device__ __forceinline__ void ldsm_x4(u32& r0, u32& r1, u32& r2, u32& r3, u32 a) {
    asm volatile("ldmatrix.sync.aligned.m8n8.x4.shared.b16 {%0,%1,%2,%3}, [%4];"
                 : "=r"(r0), "=r"(r1), "=r"(r2), "=r"(r3) : "r"(a));
}
__device__ __forceinline__ void ldsm_x2(u32& r0, u32& r1, u32 a) {
    asm volatile("ldmatrix.sync.aligned.m8n8.x2.shared.b16 {%0,%1}, [%2];"
                 : "=r"(r0), "=r"(r1) : "r"(a));
}
__device__ __forceinline__ void mma_bf16(float* d, const u32* a, const u32* b) {
    asm volatile(
        "mma.sync.aligned.m16n8k16.row.col.f32.bf16.bf16.f32 "
        "{%0,%1,%2,%3}, {%4,%5,%6,%7}, {%8,%9}, {%0,%1,%2,%3};"
        : "+f"(d[0]), "+f"(d[1]), "+f"(d[2]), "+f"(d[3])
        : "r"(a[0]), "r"(a[1]), "r"(a[2]), "r"(a[3]), "r"(b[0]), "r"(b[1]));
}
#define CPA16(d, s) \
    asm volatile("cp.async.cg.shared.global [%0], [%1], 16;" :: "r"(d), "l"(s))
#define CPC() asm volatile("cp.async.commit_group;" ::: "memory")

// ---------------------------------------------------------------------------
// fused weight/h0 conversion (one launch)
__global__ __launch_bounds__(256) void convert_wall(
    const float* __restrict__ W0, const float* __restrict__ W1,
    const float* __restrict__ W2, const float* __restrict__ W_ih,
    const float* __restrict__ Wa, const float* __restrict__ h0,
    __nv_bfloat16* __restrict__ WT,
    __nv_bfloat16* __restrict__ HB0H, __nv_bfloat16* __restrict__ HB0L)
{
    int b = blockIdx.x, tid = threadIdx.x;
    const float* src; __nv_bfloat16 *dh, *dl;
    int K, Nn, tr, e;
    if (b < 320)        { src = W0;   dh = WT + W0H;  dl = WT + W0L;  K = 320; Nn = 256; tr = 1; e = b * 256 + tid; }
    else if (b < 576)   { src = W1;   dh = WT + W1H;  dl = WT + W1L;  K = 256; Nn = 256; tr = 1; e = (b - 320) * 256 + tid; }
    else if (b < 832)   { src = W2;   dh = WT + W2H;  dl = WT + W2L;  K = 256; Nn = 256; tr = 1; e = (b - 576) * 256 + tid; }
    else if (b < 1600)  { src = W_ih; dh = WT + WIHH; dl = WT + WIHL; K = 256; Nn = 768; tr = 0; e = (b - 832) * 256 + tid; }
    else if (b < 1856)  { src = Wa;   dh = WT + WAH;  dl = WT + WAL;  K = 256; Nn = 256; tr = 1; e = (b - 1600) * 256 + tid; }
    else                { src = h0;   dh = HB0H;      dl = HB0L;      K = 256; Nn = 256; tr = 0; e = (b - 1856) * 256 + tid; }
    int n = e / K, k = e % K;
    float v = tr ? src[(long)k * Nn + n] : src[e];
    __nv_bfloat16 h = __float2bfloat16(v);
    dh[e] = h;
    dl[e] = __float2bfloat16(v - __bfloat162float(h));
}

// ---------------------------------------------------------------------------
__global__ __launch_bounds__(256) void t0_kernel(
    const float* __restrict__ p0, const float* __restrict__ M,
    const float* __restrict__ C, __nv_bfloat16* __restrict__ XINH,
    __nv_bfloat16* __restrict__ XINL, float* __restrict__ CC)
{
    int n = blockIdx.x;
    int tid = threadIdx.x;
    float v = p0[(long)n * L_ + tid];
    int any = __syncthreads_or(v != 0.f);
    float acc;
    if (!any) {
        acc = M[(long)n * L_ * H_ + tid];
        if (tid == 0) CC[n] = C[(long)n * L_];
    } else {
        __shared__ float red[256];
        __shared__ float ps[256];
        ps[tid] = v;
        __syncthreads();
        acc = 0.f;
        const float* Mn = M + (long)n * L_ * H_;
        for (int l = 0; l < L_; l++)
            acc = fmaf(ps[l], Mn[(long)l * H_ + tid], acc);
        red[tid] = ps[tid] * C[(long)n * L_ + tid];
        __syncthreads();
        for (int s = 128; s > 0; s >>= 1) {
            if (tid < s) red[tid] += red[tid + s];
            __syncthreads();
        }
        if (tid == 0) CC[n] = red[0];
    }
    __nv_bfloat16 h = __float2bfloat16(acc);
    XINH[(long)n * 320 + 64 + tid] = h;
    XINL[(long)n * 320 + 64 + tid] = __float2bfloat16(acc - __bfloat162float(h));
}

// ---------------------------------------------------------------------------
__global__ __launch_bounds__(256) void gather_kernel(
    const float* __restrict__ cond, const float* __restrict__ M,
    const float* __restrict__ C, const int* __restrict__ actions,
    __nv_bfloat16* __restrict__ XINH, __nv_bfloat16* __restrict__ XINL,
    float* __restrict__ CC)
{
    int r = threadIdx.x >> 5, lane = threadIdx.x & 31;
    long idx = (long)blockIdx.x * 8 + r;
    int t = (int)(idx / N_), n = (int)(idx % N_);
    char* dh = (char*)(XINH + idx * 320);
    char* dl = (char*)(XINL + idx * 320);
    if (lane < 16) {
        float4 v = ((const float4*)(cond + idx * COND_))[lane];
        u32 h01, l01, h23, l23;
        cvt_split(v.x, v.y, h01, l01);
        cvt_split(v.z, v.w, h23, l23);
        *(uint2*)(dh + lane * 8) = make_uint2(h01, h23);
        *(uint2*)(dl + lane * 8) = make_uint2(l01, l23);
    }
    if (t > 0) {
        int a = actions[idx - N_];
        const float4* msrc = (const float4*)(M + ((long)n * L_ + a) * H_);
#pragma unroll
        for (int i = 0; i < 2; i++) {
            float4 v = msrc[lane + i * 32];
            u32 h01, l01, h23, l23;
            cvt_split(v.x, v.y, h01, l01);
            cvt_split(v.z, v.w, h23, l23);
            int boff = 128 + lane * 8 + i * 256;
            *(uint2*)(dh + boff) = make_uint2(h01, h23);
            *(uint2*)(dl + boff) = make_uint2(l01, l23);
        }
        if (lane == 0) CC[idx] = C[(long)n * L_ + a];
    }
}

// ---------------------------------------------------------------------------
// gemm_v4 (R15-proven): bf16x3 mma.sync, 3-stage cp.async, early stage issue.
#define GEMM3_SMEM 98304

template <bool RELU, bool OUTSPLIT>
__global__ __launch_bounds__(256, 2) void gemm_v4(
    const __nv_bfloat16* __restrict__ Ah, const __nv_bfloat16* __restrict__ Al,
    const __nv_bfloat16* __restrict__ Bh, const __nv_bfloat16* __restrict__ Bl,
    const float* __restrict__ bias, float* __restrict__ C,
    __nv_bfloat16* __restrict__ Ch, __nv_bfloat16* __restrict__ Cl,
    int K, int lda, int ldc)
{
    extern __shared__ char smx[];
    u32 sb32 = (u32)__cvta_generic_to_shared(smx);

    int m0 = blockIdx.x * 128, n0 = blockIdx.y * 128;
    int tid = threadIdx.x;
    int wid = tid >> 5, lane = tid & 31;
    int warp_m = wid & 1, warp_n = wid >> 1;
    int gid = lane >> 2, tg = lane & 3;

    int sm_[2], sc_[2];
#pragma unroll
    for (int j = 0; j < 2; j++) {
        int idx = tid + j * 256;
        sm_[j] = idx >> 2; sc_[j] = idx & 3;
    }

    int rowa = warp_m * 64 + (lane & 15);
    int rsa = (rowa >> 1) & 3;
    int ha = lane >> 4;
    int rowb = warp_n * 32 + (lane & 7);
    int rsb = (rowb >> 1) & 3;
    int hb = (lane >> 3) & 1;

    float acc[4][4][4];
#pragma unroll
    for (int i = 0; i < 4; i++)
#pragma unroll
        for (int j = 0; j < 4; j++)
#pragma unroll
            for (int v = 0; v < 4; v++) acc[i][j][v] = 0.f;

    auto stage = [&](int buf, int k0) {
        u32 base = sb32 + buf * 32768;
#pragma unroll
        for (int j = 0; j < 2; j++) {
            int m = sm_[j], c = sc_[j];
            u32 off = m * 64 + ((c ^ ((m >> 1) & 3)) * 16);
            long aoff = (long)(m0 + m) * lda + k0 + c * 8;
            long boff = (long)(n0 + m) * K + k0 + c * 8;
            CPA16(base + off, Ah + aoff);
            CPA16(base + off + 8192, Al + aoff);
            CPA16(base + off + 16384, Bh + boff);
            CPA16(base + off + 24576, Bl + boff);
        }
        CPC();
    };

    int nk = K / 32;
    stage(0, 0);
    if (nk > 1) stage(1, 32); else CPC();

    for (int kt = 0; kt < nk; kt++) {
        asm volatile("cp.async.wait_group 1;" ::: "memory");
        __syncthreads();

        if (kt + 2 < nk) stage((kt + 2) % 3, (kt + 2) * 32);
        else CPC();

        u32 sbb = sb32 + (kt % 3) * 32768;
#pragma unroll
        for (int ks = 0; ks < 2; ks++) {
            u32 bhf[4][2], blf[4][2];
#pragma unroll
            for (int ni = 0; ni < 4; ni++) {
                int cb = (ks * 2 + hb) ^ rsb;
                u32 addr = sbb + 16384 + (rowb + ni * 8) * 64 + cb * 16;
                ldsm_x2(bhf[ni][0], bhf[ni][1], addr);
                ldsm_x2(blf[ni][0], blf[ni][1], addr + 8192);
            }
#pragma unroll
            for (int mi = 0; mi < 4; mi++) {
                int ca = (ks * 2 + ha) ^ rsa;
                u32 addr = sbb + (rowa + mi * 16) * 64 + ca * 16;
                u32 ah[4], al[4];
                ldsm_x4(ah[0], ah[1], ah[2], ah[3], addr);
                ldsm_x4(al[0], al[1], al[2], al[3], addr + 8192);
#pragma unroll
                for (int ni = 0; ni < 4; ni++) {
                    mma_bf16(acc[mi][ni], ah, bhf[ni]);
                    mma_bf16(acc[mi][ni], ah, blf[ni]);
                    mma_bf16(acc[mi][ni], al, bhf[ni]);
                }
            }
        }
    }

#pragma unroll
    for (int mi = 0; mi < 4; mi++) {
        int mbase = m0 + warp_m * 64 + mi * 16;
#pragma unroll
        for (int ni = 0; ni < 4; ni++) {
            int col = n0 + warp_n * 32 + ni * 8 + tg * 2;
            float b0 = 0.f, b1 = 0.f;
            if (bias) { b0 = bias[col]; b1 = bias[col + 1]; }
            float v0 = acc[mi][ni][0] + b0, v1 = acc[mi][ni][1] + b1;
            float v2 = acc[mi][ni][2] + b0, v3 = acc[mi][ni][3] + b1;
            if (RELU) {
                v0 = fmaxf(v0, 0.f); v1 = fmaxf(v1, 0.f);
                v2 = fmaxf(v2, 0.f); v3 = fmaxf(v3, 0.f);
            }
            if (OUTSPLIT) {
                u32 h01, l01;
                long o0 = (long)(mbase + gid) * ldc + col;
                long o1 = (long)(mbase + gid + 8) * ldc + col;
                cvt_split(v0, v1, h01, l01);
                *(u32*)(Ch + o0) = h01;
                *(u32*)(Cl + o0) = l01;
                cvt_split(v2, v3, h01, l01);
                *(u32*)(Ch + o1) = h01;
                *(u32*)(Cl + o1) = l01;
            } else {
                *(float2*)&C[(long)(mbase + gid) * ldc + col] = make_float2(v0, v1);
                *(float2*)&C[(long)(mbase + gid + 8) * ldc + col] = make_float2(v2, v3);
            }
        }
    }
}

// ---------------------------------------------------------------------------
// Km GEMM (R11-proven): A pre-split, B fp32 (cvt in staging), batched via z.
#define BGEMM_SMEM 32768

__global__ __launch_bounds__(256) void gemm_km(
    const __nv_bfloat16* __restrict__ Ah, const __nv_bfloat16* __restrict__ Al,
    const float* __restrict__ Bf, float* __restrict__ C,
    int K, int lda, int ldb, int ldc, long batchA, long batchB, long batchC)
{
    extern __shared__ char smx[];
    u32 sb32 = (u32)__cvta_generic_to_shared(smx);

    long bz = blockIdx.z;
    Ah += bz * batchA; Al += bz * batchA;
    Bf += bz * batchB; C += bz * batchC;

    int m0 = blockIdx.x * 128, n0 = blockIdx.y * 128;
    int tid = threadIdx.x;
    int wid = tid >> 5, lane = tid & 31;
    int warp_m = wid & 1, warp_n = wid >> 1;
    int gid = lane >> 2, tg = lane & 3;

    int bm[4], bq[4], an2[2], ac2[2];
#pragma unroll
    for (int j = 0; j < 4; j++) {
        int idx = tid + j * 256;
        bm[j] = idx >> 3; bq[j] = idx & 7;
    }
#pragma unroll
    for (int j = 0; j < 2; j++) {
        int idx = tid + j * 256;
        an2[j] = idx >> 2; ac2[j] = idx & 3;
    }

    int rowa = warp_m * 64 + (lane & 15);
    int rsa = (rowa >> 1) & 3;
    int ha = lane >> 4;
    int rowb = warp_n * 32 + (lane & 7);
    int rsb = (rowb >> 1) & 3;
    int hb = (lane >> 3) & 1;

    float acc[4][4][4];
#pragma unroll
    for (int i = 0; i < 4; i++)
#pragma unroll
        for (int j = 0; j < 4; j++)
#pragma unroll
            for (int v = 0; v < 4; v++) acc[i][j][v] = 0.f;

    auto store_a_pre = [&](int m, int c, uint4 h, uint4 l) {
        char* p = smx + m * 64 + ((c ^ ((m >> 1) & 3)) * 16);
        *(uint4*)p = h;
        *(uint4*)(p + 8192) = l;
    };
    auto store_b_f32 = [&](int m, int q, float4 v) {
        u32 h01, l01, h23, l23;
        cvt_split(v.x, v.y, h01, l01);
        cvt_split(v.z, v.w, h23, l23);
        char* p = smx + 16384 + m * 64 + (((q >> 1) ^ ((m >> 1) & 3)) * 16) + (q & 1) * 8;
        *(uint2*)p = make_uint2(h01, h23);
        *(uint2*)(p + 8192) = make_uint2(l01, l23);
    };

#pragma unroll
    for (int j = 0; j < 2; j++) {
        long off = (long)(m0 + an2[j]) * lda + ac2[j] * 8;
        store_a_pre(an2[j], ac2[j], *(const uint4*)(Ah + off), *(const uint4*)(Al + off));
    }
#pragma unroll
    for (int j = 0; j < 4; j++) {
        float4 v = *(const float4*)&Bf[(long)(n0 + bm[j]) * ldb + bq[j] * 4];
        store_b_f32(bm[j], bq[j], v);
    }
    __syncthreads();

    int nk = K / 32;
    for (int kt = 0; kt < nk; kt++) {
        float4 rbf[4];
        uint4 rah[2], ral[2];
        bool nxt = (kt + 1 < nk);
        if (nxt) {
            int k0 = (kt + 1) * 32;
#pragma unroll
            for (int j = 0; j < 2; j++) {
                long off = (long)(m0 + an2[j]) * lda + k0 + ac2[j] * 8;
                rah[j] = *(const uint4*)(Ah + off);
                ral[j] = *(const uint4*)(Al + off);
            }
#pragma unroll
            for (int j = 0; j < 4; j++)
                rbf[j] = *(const float4*)&Bf[(long)(n0 + bm[j]) * ldb + k0 + bq[j] * 4];
        }

#pragma unroll
        for (int ks = 0; ks < 2; ks++) {
            u32 bhf[4][2], blf[4][2];
#pragma unroll
            for (int ni = 0; ni < 4; ni++) {
                int cb = (ks * 2 + hb) ^ rsb;
                u32 addr = sb32 + 16384 + (rowb + ni * 8) * 64 + cb * 16;
                ldsm_x2(bhf[ni][0], bhf[ni][1], addr);
                ldsm_x2(blf[ni][0], blf[ni][1], addr + 8192);
            }
#pragma unroll
            for (int mi = 0; mi < 4; mi++) {
                int ca = (ks * 2 + ha) ^ rsa;
                u32 addr = sb32 + (rowa + mi * 16) * 64 + ca * 16;
                u32 ah[4], al[4];
                ldsm_x4(ah[0], ah[1], ah[2], ah[3], addr);
                ldsm_x4(al[0], al[1], al[2], al[3], addr + 8192);
#pragma unroll
                for (int ni = 0; ni < 4; ni++) {
                    mma_bf16(acc[mi][ni], ah, bhf[ni]);
                    mma_bf16(acc[mi][ni], ah, blf[ni]);
                    mma_bf16(acc[mi][ni], al, bhf[ni]);
                }
            }
        }
        __syncthreads();
        if (nxt) {
#pragma unroll
            for (int j = 0; j < 2; j++) store_a_pre(an2[j], ac2[j], rah[j], ral[j]);
#pragma unroll
            for (int j = 0; j < 4; j++) store_b_f32(bm[j], bq[j], rbf[j]);
        }
        __syncthreads();
    }

#pragma unroll
    for (int mi = 0; mi < 4; mi++) {
        int mbase = m0 + warp_m * 64 + mi * 16;
#pragma unroll
        for (int ni = 0; ni < 4; ni++) {
            int col = n0 + warp_n * 32 + ni * 8 + tg * 2;
            *(float2*)&C[(long)(mbase + gid) * ldc + col] =
                make_float2(acc[mi][ni][0], acc[mi][ni][1]);
            *(float2*)&C[(long)(mbase + gid + 8) * ldc + col] =
                make_float2(acc[mi][ni][2], acc[mi][ni][3]);
        }
    }
}

// ---------------------------------------------------------------------------
// persistent GRU: tensor-core gh, 384 threads, one-hop barrier,
// 6-way split accumulators (3 planes x 2 s-parity) to break the HMMA chain.
#define GRU_SMEM2 43008
#define GRU_THREADS 384

__device__ __forceinline__ float sigmf(float x) { return 1.f / (1.f + __expf(-x)); }
__device__ __forceinline__ float tanhfast(float x) { return 2.f / (1.f + __expf(-2.f * x)) - 1.f; }

__global__ __launch_bounds__(GRU_THREADS) void gru_tc(
    const float* __restrict__ GI, const float* __restrict__ h0,
    const float* __restrict__ W_hh, const float* __restrict__ b_hh,
    const __nv_bfloat16* __restrict__ HB0H, const __nv_bfloat16* __restrict__ HB0L,
    __nv_bfloat16* __restrict__ HBH, __nv_bfloat16* __restrict__ HBL)
{
    extern __shared__ char sm8[];
    u32 sb = (u32)__cvta_generic_to_shared(sm8);
    float* ghs = (float*)(sm8 + 32768);
    float* hown = (float*)(sm8 + 40960);

    int tid = threadIdx.x;
    int wid = tid >> 5, lane = tid & 31;
    int jt = blockIdx.x & 15, nt = blockIdx.x >> 4;
    int j0 = jt * 16, n0 = nt * 32;
    int colg = wid % 6, mt = wid / 6;

    unsigned* arr = &g_bar2[nt * 32];

    u32 bhf[16][2], blf[16][2];
    {
        for (int e = tid; e < 3072; e += GRU_THREADS) {
            int r = e >> 6, q = e & 63;
            float4 v = *(const float4*)&W_hh[(long)((r >> 4) * 256 + j0 + (r & 15)) * 256 + q * 4];
            u32 h01, l01, h23, l23;
            cvt_split(v.x, v.y, h01, l01);
            cvt_split(v.z, v.w, h23, l23);
            *(uint2*)(sm8 + r * 512 + (((q >> 1) ^ (r & 7)) * 16) + (q & 1) * 8) =
                make_uint2(h01, h23);
        }
        __syncthreads();
        {
            int rb = colg * 8 + (lane & 7);
            int hb2 = (lane >> 3) & 1;
#pragma unroll
            for (int s = 0; s < 16; s++) {
                u32 addr = sb + rb * 512 + (((s * 2 + hb2) ^ (rb & 7)) * 16);
                ldsm_x2(bhf[s][0], bhf[s][1], addr);
            }
        }
        __syncthreads();
        for (int e = tid; e < 3072; e += GRU_THREADS) {
            int r = e >> 6, q = e & 63;
            float4 v = *(const float4*)&W_hh[(long)((r >> 4) * 256 + j0 + (r & 15)) * 256 + q * 4];
            u32 h01, l01, h23, l23;
            cvt_split(v.x, v.y, h01, l01);
            cvt_split(v.z, v.w, h23, l23);
            *(uint2*)(sm8 + r * 512 + (((q >> 1) ^ (r & 7)) * 16) + (q & 1) * 8) =
                make_uint2(l01, l23);
        }
        __syncthreads();
        {
            int rb = colg * 8 + (lane & 7);
            int hb2 = (lane >> 3) & 1;
#pragma unroll
            for (int s = 0; s < 16; s++) {
                u32 addr = sb + rb * 512 + (((s * 2 + hb2) ^ (rb & 7)) * 16);
                ldsm_x2(blf[s][0], blf[s][1], addr);
            }
        }
        __syncthreads();
    }

    int jj = tid & 15, nb0 = (tid & 255) >> 4;
    float bhr = b_hh[j0 + jj], bhz = b_hh[256 + j0 + jj], bhn = b_hh[512 + j0 + jj];
    if (tid < 256) {
#pragma unroll
        for (int i = 0; i < 2; i++) {
            int n = nb0 + 16 * i;
            hown[n * 16 + jj] = h0[(long)(n0 + n) * H_ + j0 + jj];
        }
    }
    float gr[2], gz[2], gn[2];
    if (tid < 256) {
#pragma unroll
        for (int i = 0; i < 2; i++) {
            long base = ((long)(n0 + nb0 + 16 * i)) * 768 + j0 + jj;
            gr[i] = GI[base]; gz[i] = GI[base + 256]; gn[i] = GI[base + 512];
        }
    }
    __syncthreads();

    for (int t = 0; t < T_; t++) {
        const __nv_bfloat16* srcH = t ? HBH + (long)(t - 1) * N_ * H_ : HB0H;
        const __nv_bfloat16* srcL = t ? HBL + (long)(t - 1) * N_ * H_ : HB0L;
        for (int e = tid; e < 1024; e += GRU_THREADS) {
            int r = e >> 5, c = e & 31;
            u32 soff = r * 512 + ((c ^ (r & 7)) * 16);
            *(uint4*)(sm8 + soff) = *(const uint4*)(srcH + (long)(n0 + r) * 256 + c * 8);
            *(uint4*)(sm8 + 16384 + soff) = *(const uint4*)(srcL + (long)(n0 + r) * 256 + c * 8);
        }
        __syncthreads();

        {
            // 6 independent accumulators: [plane][s-parity]
            float a_hh[2][4], a_hl[2][4], a_lh[2][4];
#pragma unroll
            for (int p = 0; p < 2; p++)
#pragma unroll
                for (int v = 0; v < 4; v++) {
                    a_hh[p][v] = 0.f; a_hl[p][v] = 0.f; a_lh[p][v] = 0.f;
                }
            int rr = mt * 16 + (lane & 15);
            int ha2 = lane >> 4;
#pragma unroll
            for (int s = 0; s < 16; s++) {
                int p = s & 1;
                u32 addr = sb + rr * 512 + (((s * 2 + ha2) ^ (rr & 7)) * 16);
                u32 ah[4], al[4];
                ldsm_x4(ah[0], ah[1], ah[2], ah[3], addr);
                ldsm_x4(al[0], al[1], al[2], al[3], addr + 16384);
                mma_bf16(a_hh[p], ah, bhf[s]);
                mma_bf16(a_hl[p], ah, blf[s]);
                mma_bf16(a_lh[p], al, bhf[s]);
            }
            float accv[4];
#pragma unroll
            for (int v = 0; v < 4; v++)
                accv[v] = ((a_hh[0][v] + a_hh[1][v]) + (a_hl[0][v] + a_hl[1][v]))
                        + (a_lh[0][v] + a_lh[1][v]);
            int gid = lane >> 2, tg = lane & 3;
            *(float2*)&ghs[(mt * 16 + gid) * 64 + colg * 8 + tg * 2] =
                make_float2(accv[0], accv[1]);
            *(float2*)&ghs[(mt * 16 + gid + 8) * 64 + colg * 8 + tg * 2] =
                make_float2(accv[2], accv[3]);
        }
        __syncthreads();

        if (tid < 256) {
            __nv_bfloat16* bhd = HBH + (long)t * N_ * H_;
            __nv_bfloat16* bld = HBL + (long)t * N_ * H_;
#pragma unroll
            for (int i = 0; i < 2; i++) {
                int n = nb0 + 16 * i;
                float ghr = ghs[n * 64 + jj];
                float ghz = ghs[n * 64 + 16 + jj];
                float ghn = ghs[n * 64 + 32 + jj];
                float rg = sigmf(gr[i] + ghr + bhr);
                float z  = sigmf(gz[i] + ghz + bhz);
                float nv = tanhfast(gn[i] + rg * (ghn + bhn));
                float hp = hown[n * 16 + jj];
                float hn = (1.f - z) * nv + z * hp;
                hown[n * 16 + jj] = hn;
                long gofs = (long)(n0 + n) * H_ + j0 + jj;
                __nv_bfloat16 hh = __float2bfloat16(hn);
                bhd[gofs] = hh;
                bld[gofs] = __float2bfloat16(hn - __bfloat162float(hh));
            }
        }

        if (t < T_ - 1) {
            __syncthreads();
            if (tid == 0) {
                asm volatile("red.release.gpu.global.add.u32 [%0], %1;"
                             :: "l"(arr), "r"(1u) : "memory");
            }
            if (tid < 256) {
#pragma unroll
                for (int i = 0; i < 2; i++) {
                    long base = ((long)(t + 1) * N_ + n0 + nb0 + 16 * i) * 768 + j0 + jj;
                    gr[i] = GI[base]; gz[i] = GI[base + 256]; gn[i] = GI[base + 512];
                }
            }
            if (tid == 0) {
                unsigned target = (unsigned)(t + 1) * 16u;
                unsigned e;
                do {
                    asm volatile("ld.acquire.gpu.global.u32 %0, [%1];"
                                 : "=r"(e) : "l"(arr) : "memory");
                } while (e < target);
            }
            __syncthreads();
        }
    }
}

// ---------------------------------------------------------------------------
__global__ __launch_bounds__(256) void epilogue_kernel(
    const float* __restrict__ WB, const float* __restrict__ CC,
    const int* __restrict__ actions, const float* __restrict__ Wc,
    const float* __restrict__ bc,
    const __nv_bfloat16* __restrict__ HBH, const __nv_bfloat16* __restrict__ HBL,
    float* __restrict__ out)
{
    int wid = threadIdx.x >> 5, lane = threadIdx.x & 31;
    long idx = (long)blockIdx.x * 8 + wid;
    int t = (int)(idx / N_), n = (int)(idx % N_);
    float cc = CC[idx];
    long base = idx * OUTW_;

    const __nv_bfloat162* hv = (const __nv_bfloat162*)(HBH + idx * 256 + lane * 8);
    const __nv_bfloat162* lv = (const __nv_bfloat162*)(HBL + idx * 256 + lane * 8);
    float h[8];
#pragma unroll
    for (int i = 0; i < 4; i++) {
        float2 fh = __bfloat1622float2(hv[i]);
        float2 fl = __bfloat1622float2(lv[i]);
        h[2 * i] = fh.x + fl.x;
        h[2 * i + 1] = fh.y + fl.y;
    }
    float2* hdst = (float2*)(out + base + 2 + lane * 8);
#pragma unroll
    for (int i = 0; i < 4; i++) hdst[i] = make_float2(h[2 * i], h[2 * i + 1]);

    const float4* wc = (const float4*)Wc;
    float4 c0 = wc[lane * 2], c1 = wc[lane * 2 + 1];
    float d = h[0] * c0.x + h[1] * c0.y + h[2] * c0.z + h[3] * c0.w
            + h[4] * c1.x + h[5] * c1.y + h[6] * c1.z + h[7] * c1.w;
#pragma unroll
    for (int o = 16; o; o >>= 1) d += __shfl_xor_sync(~0u, d, o);

    const float4* wrow = (const float4*)(WB + ((long)n * T_ + t) * L_);
    float4 w0 = wrow[lane * 2], w1 = wrow[lane * 2 + 1];
    float wv[8] = {w0.x * cc, w0.y * cc, w0.z * cc, w0.w * cc,
                   w1.x * cc, w1.y * cc, w1.z * cc, w1.w * cc};
    float mx = wv[0];
#pragma unroll
    for (int i = 1; i < 8; i++) mx = fmaxf(mx, wv[i]);
#pragma unroll
    for (int o = 16; o; o >>= 1) mx = fmaxf(mx, __shfl_xor_sync(~0u, mx, o));
    float e[8], s = 0.f;
#pragma unroll
    for (int i = 0; i < 8; i++) { e[i] = expf(wv[i] - mx); s += e[i]; }
#pragma unroll
    for (int o = 16; o; o >>= 1) s += __shfl_xor_sync(~0u, s, o);
    float inv = 1.f / s;

    int a = actions[idx];
    float2* pdst = (float2*)(out + base + 258 + lane * 8);
    float2* odst = (float2*)(out + base + 514 + lane * 8);
#pragma unroll
    for (int i = 0; i < 4; i++) {
        pdst[i] = make_float2(e[2 * i] * inv, e[2 * i + 1] * inv);
        int l0 = lane * 8 + 2 * i;
        odst[i] = make_float2(l0 == a ? 1.f : 0.f, l0 + 1 == a ? 1.f : 0.f);
    }
    if (lane == 0) {
        out[base + 0] = (float)a;
        out[base + 1] = d + bc[0];
    }
}

// ---------------------------------------------------------------------------
extern "C" void kernel_launch(void* const* d_in, const int* in_sizes, int n_in,
                              void* d_out, int out_size)
{
    const float* cond = (const float*)d_in[0];
    const float* M    = (const float*)d_in[1];
    const float* Km   = (const float*)d_in[2];
    const float* Cm   = (const float*)d_in[3];
    const float* h0   = (const float*)d_in[4];
    const float* p0   = (const float*)d_in[5];
    const float* W0   = (const float*)d_in[6];
    const float* b0   = (const float*)d_in[7];
    const float* W1   = (const float*)d_in[8];
    const float* b1   = (const float*)d_in[9];
    const float* W2   = (const float*)d_in[10];
    const float* b2   = (const float*)d_in[11];
    const float* W_ih = (const float*)d_in[12];
    const float* W_hh = (const float*)d_in[13];
    const float* b_ih = (const float*)d_in[14];
    const float* b_hh = (const float*)d_in[15];
    const float* Wa   = (const float*)d_in[16];
    const float* ba   = (const float*)d_in[17];
    const float* Wc   = (const float*)d_in[18];
    const float* bc   = (const float*)d_in[19];
    const int* actions = (const int*)d_in[20];
    float* out = (float*)d_out;

    float* base = nullptr;
    cudaGetSymbolAddress((void**)&base, g_scratch);
    __nv_bfloat16* XINH = (__nv_bfloat16*)(base + XINH_OFF);
    __nv_bfloat16* XINL = (__nv_bfloat16*)(base + XINL_OFF);
    __nv_bfloat16* XAH = (__nv_bfloat16*)(base + XAH_OFF);
    __nv_bfloat16* XAL = (__nv_bfloat16*)(base + XAL_OFF);
    __nv_bfloat16* XBH = (__nv_bfloat16*)(base + XBH_OFF);
    __nv_bfloat16* XBL = (__nv_bfloat16*)(base + XBL_OFF);
    float* GI = base + GI_OFF;
    __nv_bfloat16* KBH = (__nv_bfloat16*)(base + KBH_OFF);
    __nv_bfloat16* KBL = (__nv_bfloat16*)(base + KBL_OFF);
    float* WB = base + WB_OFF;
    float* CC = base + CC_OFF;
    __nv_bfloat16* WT = (__nv_bfloat16*)(base + WT_OFF);
    __nv_bfloat16* HBH = (__nv_bfloat16*)(base + HBH_OFF);
    __nv_bfloat16* HBL = (__nv_bfloat16*)(base + HBL_OFF);
    __nv_bfloat16* HB0H = (__nv_bfloat16*)(base + HB0H_OFF);
    __nv_bfloat16* HB0L = (__nv_bfloat16*)(base + HB0L_OFF);

    void* bar_addr = nullptr;
    cudaGetSymbolAddress(&bar_addr, g_bar2);

    cudaFuncSetAttribute(gru_tc,
                         cudaFuncAttributeMaxDynamicSharedMemorySize, GRU_SMEM2);
    cudaFuncSetAttribute(gemm_v4<true, true>,
                         cudaFuncAttributeMaxDynamicSharedMemorySize, GEMM3_SMEM);
    cudaFuncSetAttribute(gemm_v4<false, false>,
                         cudaFuncAttributeMaxDynamicSharedMemorySize, GEMM3_SMEM);
    cudaFuncSetAttribute(gemm_v4<false, true>,
                         cudaFuncAttributeMaxDynamicSharedMemorySize, GEMM3_SMEM);

    // phase 0: weight/h0 conversion
    convert_wall<<<2112, 256>>>(W0, W1, W2, W_ih, Wa, h0, WT, HB0H, HB0L);

    // phase A (activations carried as bf16 hi/lo)
    t0_kernel<<<N_, 256>>>(p0, M, Cm, XINH, XINL, CC);
    gather_kernel<<<ROWS_ / 8, 256>>>(cond, M, Cm, actions, XINH, XINL, CC);
    gemm_v4<true, true><<<dim3(ROWS_ / 128, 2), 256, GEMM3_SMEM>>>(
        XINH, XINL, WT + W0H, WT + W0L, b0, nullptr, XAH, XAL, 320, 320, 256);
    gemm_v4<true, true><<<dim3(ROWS_ / 128, 2), 256, GEMM3_SMEM>>>(
        XAH, XAL, WT + W1H, WT + W1L, b1, nullptr, XBH, XBL, 256, 256, 256);
    gemm_v4<true, true><<<dim3(ROWS_ / 128, 2), 256, GEMM3_SMEM>>>(
        XBH, XBL, WT + W2H, WT + W2L, b2, nullptr, XAH, XAL, 256, 256, 256);
    gemm_v4<false, false><<<dim3(ROWS_ / 128, 6), 256, GEMM3_SMEM>>>(
        XAH, XAL, WT + WIHH, WT + WIHL, b_ih, GI, nullptr, nullptr, 256, 256, 768);

    // phase B: persistent tensor-core GRU
    cudaMemsetAsync(bar_addr, 0, 8 * 32 * sizeof(unsigned));
    gru_tc<<<128, GRU_THREADS, GRU_SMEM2>>>(GI, h0, W_hh, b_hh, HB0H, HB0L, HBH, HBL);

    // phase C
    gemm_v4<false, true><<<dim3(ROWS_ / 128, 2), 256, GEMM3_SMEM>>>(
        HBH, HBL, WT + WAH, WT + WAL, ba, nullptr, KBH, KBL, 256, 256, 256);
    gemm_km<<<dim3(1, 2, 256), 256, BGEMM_SMEM>>>(
        KBH, KBL, Km, WB, 256, 256, 256, 256,
        (long)T_ * 256, (long)L_ * H_, (long)T_ * L_);
    epilogue_kernel<<<ROWS_ / 8, 256>>>(WB, CC, actions, Wc, bc, HBH, HBL, out);
}

// round 17
// speedup vs baseline: 1.0039x; 1.0039x over previous
#include <cuda_runtime.h>
#include <cuda_bf16.h>
#include <math.h>

#define T_ 128
#define N_ 256
#define L_ 256
#define H_ 256
#define COND_ 64
#define ROWS_ (T_ * N_)   // 32768
#define OUTW_ 770

typedef unsigned long long u64;
typedef unsigned u32;

// ---------------- scratch (float units) --------------------------------------
#define R0_OFF   0L                               // fp32 [N][256]
#define XAH_OFF  (R0_OFF + (long)N_ * 256)        // [ROWS][256] bf16
#define XAL_OFF  (XAH_OFF + (long)ROWS_ * 128)
#define XBH_OFF  (XAL_OFF + (long)ROWS_ * 128)
#define XBL_OFF  (XBH_OFF + (long)ROWS_ * 128)
#define GI_OFF   (XBL_OFF + (long)ROWS_ * 128)    // fp32 [ROWS][768]
#define KBH_OFF  (GI_OFF + (long)ROWS_ * 768)
#define KBL_OFF  (KBH_OFF + (long)ROWS_ * 128)
#define WB_OFF   (KBL_OFF + (long)ROWS_ * 128)    // fp32 [N][T][L]
#define CC_OFF   (WB_OFF + (long)ROWS_ * 256)
#define WT_OFF   (CC_OFF + (long)ROWS_)
#define WT_FLOATS 475136L
#define HBH_OFF  (WT_OFF + WT_FLOATS)
#define HBL_OFF  (HBH_OFF + 4194304L)
#define HB0H_OFF (HBL_OFF + 4194304L)
#define HB0L_OFF (HB0H_OFF + 32768L)
#define SCRATCH_FLOATS (HB0L_OFF + 32768L)

__device__ float g_scratch[SCRATCH_FLOATS];
__device__ unsigned g_bar2[8 * 32];   // per-nt arrive counters (monotonic)

// bf16 weight-buffer offsets (bf16 element units inside WT)
#define W0H 0
#define W0L 81920
#define W1H 163840
#define W1L 229376
#define W2H 294912
#define W2L 360448
#define WIHH 425984
#define WIHL 622592
#define WAH 819200
#define WAL 884736

// ---------------- bf16 helpers ------------------------------------------------
__device__ __forceinline__ void cvt_split(float x0, float x1, u32& h, u32& l) {
    u32 hh;
    asm("cvt.rn.bf16x2.f32 %0, %1, %2;" : "=r"(hh) : "f"(x1), "f"(x0));
    float r0 = x0 - __uint_as_float(hh << 16);
    float r1 = x1 - __uint_as_float(hh & 0xFFFF0000u);
    u32 ll;
    asm("cvt.rn.bf16x2.f32 %0, %1, %2;" : "=r"(ll) : "f"(r1), "f"(r0));
    h = hh; l = ll;
}
__device__ __forceinline__ void ldsm_x4(u32& r0, u32& r1, u32& r2, u32& r3, u32 a) {
    asm volatile("ldmatrix.sync.aligned.m8n8.x4.shared.b16 {%0,%1,%2,%3}, [%4];"
                 : "=r"(r0), "=r"(r1), "=r"(r2), "=r"(r3) : "r"(a));
}
__device__ __forceinline__ void ldsm_x2(u32& r0, u32& r1, u32 a) {
    asm volatile("ldmatrix.sync.aligned.m8n8.x2.shared.b16 {%0,%1}, [%2];"
                 : "=r"(r0), "=r"(r1) : "r"(a));
}
__device__ __forceinline__ void mma_bf16(float* d, const u32* a, const u32* b) {
    asm volatile(
        "mma.sync.aligned.m16n8k16.row.col.f32.bf16.bf16.f32 "
        "{%0,%1,%2,%3}, {%4,%5,%6,%7}, {%8,%9}, {%0,%1,%2,%3};"
        : "+f"(d[0]), "+f"(d[1]), "+f"(d[2]), "+f"(d[3])
        : "r"(a[0]), "r"(a[1]), "r"(a[2]), "r"(a[3]), "r"(b[0]), "r"(b[1]));
}
#define CPA16(d, s) \
    asm volatile("cp.async.cg.shared.global [%0], [%1], 16;" :: "r"(d), "l"(s))
#define CPC() asm volatile("cp.async.commit_group;" ::: "memory")

// ---------------------------------------------------------------------------
// fused weight/h0 conversion (one launch)
__global__ __launch_bounds__(256) void convert_wall(
    const float* __restrict__ W0, const float* __restrict__ W1,
    const float* __restrict__ W2, const float* __restrict__ W_ih,
    const float* __restrict__ Wa, const float* __restrict__ h0,
    __nv_bfloat16* __restrict__ WT,
    __nv_bfloat16* __restrict__ HB0H, __nv_bfloat16* __restrict__ HB0L)
{
    int b = blockIdx.x, tid = threadIdx.x;
    const float* src; __nv_bfloat16 *dh, *dl;
    int K, Nn, tr, e;
    if (b < 320)        { src = W0;   dh = WT + W0H;  dl = WT + W0L;  K = 320; Nn = 256; tr = 1; e = b * 256 + tid; }
    else if (b < 576)   { src = W1;   dh = WT + W1H;  dl = WT + W1L;  K = 256; Nn = 256; tr = 1; e = (b - 320) * 256 + tid; }
    else if (b < 832)   { src = W2;   dh = WT + W2H;  dl = WT + W2L;  K = 256; Nn = 256; tr = 1; e = (b - 576) * 256 + tid; }
    else if (b < 1600)  { src = W_ih; dh = WT + WIHH; dl = WT + WIHL; K = 256; Nn = 768; tr = 0; e = (b - 832) * 256 + tid; }
    else if (b < 1856)  { src = Wa;   dh = WT + WAH;  dl = WT + WAL;  K = 256; Nn = 256; tr = 1; e = (b - 1600) * 256 + tid; }
    else                { src = h0;   dh = HB0H;      dl = HB0L;      K = 256; Nn = 256; tr = 0; e = (b - 1856) * 256 + tid; }
    int n = e / K, k = e % K;
    float v = tr ? src[(long)k * Nn + n] : src[e];
    __nv_bfloat16 h = __float2bfloat16(v);
    dh[e] = h;
    dl[e] = __float2bfloat16(v - __bfloat162float(h));
}

// ---------------------------------------------------------------------------
// t0: R0[n][:] = p_init @ M[n], CC[n] = p_init . C[n]
__global__ __launch_bounds__(256) void t0_kernel(
    const float* __restrict__ p0, const float* __restrict__ M,
    const float* __restrict__ C, float* __restrict__ R0, float* __restrict__ CC)
{
    int n = blockIdx.x;
    int tid = threadIdx.x;
    float v = p0[(long)n * L_ + tid];
    int any = __syncthreads_or(v != 0.f);
    float acc;
    if (!any) {
        acc = M[(long)n * L_ * H_ + tid];
        if (tid == 0) CC[n] = C[(long)n * L_];
    } else {
        __shared__ float red[256];
        __shared__ float ps[256];
        ps[tid] = v;
        __syncthreads();
        acc = 0.f;
        const float* Mn = M + (long)n * L_ * H_;
        for (int l = 0; l < L_; l++)
            acc = fmaf(ps[l], Mn[(long)l * H_ + tid], acc);
        red[tid] = ps[tid] * C[(long)n * L_ + tid];
        __syncthreads();
        for (int s = 128; s > 0; s >>= 1) {
            if (tid < s) red[tid] += red[tid + s];
            __syncthreads();
        }
        if (tid == 0) CC[n] = red[0];
    }
    R0[(long)n * 256 + tid] = acc;
}

// ---------------------------------------------------------------------------
// CC fill for t>0 (tiny)
__global__ __launch_bounds__(256) void cc_kernel(
    const float* __restrict__ C, const int* __restrict__ actions,
    float* __restrict__ CC)
{
    long idx = (long)N_ + blockIdx.x * 256 + threadIdx.x;  // t>=1
    int n = (int)(idx & 255);
    int a = actions[idx - N_];
    CC[idx] = C[(long)n * L_ + a];
}

// ---------------------------------------------------------------------------
// gemm_v4: bf16x3 mma.sync, 3-stage cp.async (B), early stage issue.
// GATHER: A is built inline from cond/M/R0/actions (fp32 -> split in staging).
#define GEMM3_SMEM 98304

template <bool RELU, bool OUTSPLIT, bool GATHER>
__global__ __launch_bounds__(256, 2) void gemm_v4(
    const __nv_bfloat16* __restrict__ Ah, const __nv_bfloat16* __restrict__ Al,
    const float* __restrict__ cond, const float* __restrict__ Mg,
    const float* __restrict__ R0, const int* __restrict__ acts,
    const __nv_bfloat16* __restrict__ Bh, const __nv_bfloat16* __restrict__ Bl,
    const float* __restrict__ bias, float* __restrict__ C,
    __nv_bfloat16* __restrict__ Ch, __nv_bfloat16* __restrict__ Cl,
    int K, int lda, int ldc)
{
    extern __shared__ char smx[];
    u32 sb32 = (u32)__cvta_generic_to_shared(smx);

    int m0 = blockIdx.x * 128, n0 = blockIdx.y * 128;
    int tid = threadIdx.x;
    int wid = tid >> 5, lane = tid & 31;
    int warp_m = wid & 1, warp_n = wid >> 1;
    int gid = lane >> 2, tg = lane & 3;

    int sm_[2], sc_[2];
#pragma unroll
    for (int j = 0; j < 2; j++) {
        int idx = tid + j * 256;
        sm_[j] = idx >> 2; sc_[j] = idx & 3;
    }

    int rowa = warp_m * 64 + (lane & 15);
    int rsa = (rowa >> 1) & 3;
    int ha = lane >> 4;
    int rowb = warp_n * 32 + (lane & 7);
    int rsb = (rowb >> 1) & 3;
    int hb = (lane >> 3) & 1;

    float acc[4][4][4];
#pragma unroll
    for (int i = 0; i < 4; i++)
#pragma unroll
        for (int j = 0; j < 4; j++)
#pragma unroll
            for (int v = 0; v < 4; v++) acc[i][j][v] = 0.f;

    auto stage = [&](int buf, int k0) {
        u32 base = sb32 + buf * 32768;
#pragma unroll
        for (int j = 0; j < 2; j++) {
            int m = sm_[j], c = sc_[j];
            u32 off = m * 64 + ((c ^ ((m >> 1) & 3)) * 16);
            long boff = (long)(n0 + m) * K + k0 + c * 8;
            CPA16(base + off + 16384, Bh + boff);
            CPA16(base + off + 24576, Bl + boff);
            if (!GATHER) {
                long aoff = (long)(m0 + m) * lda + k0 + c * 8;
                CPA16(base + off, Ah + aoff);
                CPA16(base + off + 8192, Al + aoff);
            }
        }
        CPC();
        if (GATHER) {
#pragma unroll
            for (int j = 0; j < 2; j++) {
                int m = sm_[j], c = sc_[j];
                long idx = m0 + m;
                int t = (int)(idx >> 8), n = (int)(idx & 255);
                int k = k0 + c * 8;
                float4 v0, v1;
                if (k < 64) {
                    const float4* cs = (const float4*)(cond + idx * COND_ + k);
                    v0 = cs[0]; v1 = cs[1];
                } else {
                    int kk = k - 64;
                    const float* src;
                    if (t == 0) {
                        src = R0 + (long)n * 256 + kk;
                    } else {
                        int a = acts[idx - N_];
                        src = Mg + ((long)n * L_ + a) * H_ + kk;
                    }
                    v0 = *(const float4*)src;
                    v1 = *(const float4*)(src + 4);
                }
                u32 h01, l01, h23, l23;
                u32 off = m * 64 + ((c ^ ((m >> 1) & 3)) * 16);
                char* p = smx + buf * 32768 + off;
                cvt_split(v0.x, v0.y, h01, l01);
                cvt_split(v0.z, v0.w, h23, l23);
                *(uint2*)p = make_uint2(h01, h23);
                *(uint2*)(p + 8192) = make_uint2(l01, l23);
                cvt_split(v1.x, v1.y, h01, l01);
                cvt_split(v1.z, v1.w, h23, l23);
                *(uint2*)(p + 8) = make_uint2(h01, h23);
                *(uint2*)(p + 8192 + 8) = make_uint2(l01, l23);
            }
        }
    };

    int nk = K / 32;
    stage(0, 0);
    if (nk > 1) stage(1, 32); else CPC();

    for (int kt = 0; kt < nk; kt++) {
        asm volatile("cp.async.wait_group 1;" ::: "memory");
        __syncthreads();

        if (kt + 2 < nk) stage((kt + 2) % 3, (kt + 2) * 32);
        else CPC();

        u32 sbb = sb32 + (kt % 3) * 32768;
#pragma unroll
        for (int ks = 0; ks < 2; ks++) {
            u32 bhf[4][2], blf[4][2];
#pragma unroll
            for (int ni = 0; ni < 4; ni++) {
                int cb = (ks * 2 + hb) ^ rsb;
                u32 addr = sbb + 16384 + (rowb + ni * 8) * 64 + cb * 16;
                ldsm_x2(bhf[ni][0], bhf[ni][1], addr);
                ldsm_x2(blf[ni][0], blf[ni][1], addr + 8192);
            }
#pragma unroll
            for (int mi = 0; mi < 4; mi++) {
                int ca = (ks * 2 + ha) ^ rsa;
                u32 addr = sbb + (rowa + mi * 16) * 64 + ca * 16;
                u32 ah[4], al[4];
                ldsm_x4(ah[0], ah[1], ah[2], ah[3], addr);
                ldsm_x4(al[0], al[1], al[2], al[3], addr + 8192);
#pragma unroll
                for (int ni = 0; ni < 4; ni++) {
                    mma_bf16(acc[mi][ni], ah, bhf[ni]);
                    mma_bf16(acc[mi][ni], ah, blf[ni]);
                    mma_bf16(acc[mi][ni], al, bhf[ni]);
                }
            }
        }
    }

#pragma unroll
    for (int mi = 0; mi < 4; mi++) {
        int mbase = m0 + warp_m * 64 + mi * 16;
#pragma unroll
        for (int ni = 0; ni < 4; ni++) {
            int col = n0 + warp_n * 32 + ni * 8 + tg * 2;
            float b0 = 0.f, b1 = 0.f;
            if (bias) { b0 = bias[col]; b1 = bias[col + 1]; }
            float v0 = acc[mi][ni][0] + b0, v1 = acc[mi][ni][1] + b1;
            float v2 = acc[mi][ni][2] + b0, v3 = acc[mi][ni][3] + b1;
            if (RELU) {
                v0 = fmaxf(v0, 0.f); v1 = fmaxf(v1, 0.f);
                v2 = fmaxf(v2, 0.f); v3 = fmaxf(v3, 0.f);
            }
            if (OUTSPLIT) {
                u32 h01, l01;
                long o0 = (long)(mbase + gid) * ldc + col;
                long o1 = (long)(mbase + gid + 8) * ldc + col;
                cvt_split(v0, v1, h01, l01);
                *(u32*)(Ch + o0) = h01;
                *(u32*)(Cl + o0) = l01;
                cvt_split(v2, v3, h01, l01);
                *(u32*)(Ch + o1) = h01;
                *(u32*)(Cl + o1) = l01;
            } else {
                *(float2*)&C[(long)(mbase + gid) * ldc + col] = make_float2(v0, v1);
                *(float2*)&C[(long)(mbase + gid + 8) * ldc + col] = make_float2(v2, v3);
            }
        }
    }
}

// ---------------------------------------------------------------------------
// Km GEMM (R11-proven): A pre-split, B fp32 (cvt in staging), batched via z.
#define BGEMM_SMEM 32768

__global__ __launch_bounds__(256) void gemm_km(
    const __nv_bfloat16* __restrict__ Ah, const __nv_bfloat16* __restrict__ Al,
    const float* __restrict__ Bf, float* __restrict__ C,
    int K, int lda, int ldb, int ldc, long batchA, long batchB, long batchC)
{
    extern __shared__ char smx[];
    u32 sb32 = (u32)__cvta_generic_to_shared(smx);

    long bz = blockIdx.z;
    Ah += bz * batchA; Al += bz * batchA;
    Bf += bz * batchB; C += bz * batchC;

    int m0 = blockIdx.x * 128, n0 = blockIdx.y * 128;
    int tid = threadIdx.x;
    int wid = tid >> 5, lane = tid & 31;
    int warp_m = wid & 1, warp_n = wid >> 1;
    int gid = lane >> 2, tg = lane & 3;

    int bm[4], bq[4], an2[2], ac2[2];
#pragma unroll
    for (int j = 0; j < 4; j++) {
        int idx = tid + j * 256;
        bm[j] = idx >> 3; bq[j] = idx & 7;
    }
#pragma unroll
    for (int j = 0; j < 2; j++) {
        int idx = tid + j * 256;
        an2[j] = idx >> 2; ac2[j] = idx & 3;
    }

    int rowa = warp_m * 64 + (lane & 15);
    int rsa = (rowa >> 1) & 3;
    int ha = lane >> 4;
    int rowb = warp_n * 32 + (lane & 7);
    int rsb = (rowb >> 1) & 3;
    int hb = (lane >> 3) & 1;

    float acc[4][4][4];
#pragma unroll
    for (int i = 0; i < 4; i++)
#pragma unroll
        for (int j = 0; j < 4; j++)
#pragma unroll
            for (int v = 0; v < 4; v++) acc[i][j][v] = 0.f;

    auto store_a_pre = [&](int m, int c, uint4 h, uint4 l) {
        char* p = smx + m * 64 + ((c ^ ((m >> 1) & 3)) * 16);
        *(uint4*)p = h;
        *(uint4*)(p + 8192) = l;
    };
    auto store_b_f32 = [&](int m, int q, float4 v) {
        u32 h01, l01, h23, l23;
        cvt_split(v.x, v.y, h01, l01);
        cvt_split(v.z, v.w, h23, l23);
        char* p = smx + 16384 + m * 64 + (((q >> 1) ^ ((m >> 1) & 3)) * 16) + (q & 1) * 8;
        *(uint2*)p = make_uint2(h01, h23);
        *(uint2*)(p + 8192) = make_uint2(l01, l23);
    };

#pragma unroll
    for (int j = 0; j < 2; j++) {
        long off = (long)(m0 + an2[j]) * lda + ac2[j] * 8;
        store_a_pre(an2[j], ac2[j], *(const uint4*)(Ah + off), *(const uint4*)(Al + off));
    }
#pragma unroll
    for (int j = 0; j < 4; j++) {
        float4 v = *(const float4*)&Bf[(long)(n0 + bm[j]) * ldb + bq[j] * 4];
        store_b_f32(bm[j], bq[j], v);
    }
    __syncthreads();

    int nk = K / 32;
    for (int kt = 0; kt < nk; kt++) {
        float4 rbf[4];
        uint4 rah[2], ral[2];
        bool nxt = (kt + 1 < nk);
        if (nxt) {
            int k0 = (kt + 1) * 32;
#pragma unroll
            for (int j = 0; j < 2; j++) {
                long off = (long)(m0 + an2[j]) * lda + k0 + ac2[j] * 8;
                rah[j] = *(const uint4*)(Ah + off);
                ral[j] = *(const uint4*)(Al + off);
            }
#pragma unroll
            for (int j = 0; j < 4; j++)
                rbf[j] = *(const float4*)&Bf[(long)(n0 + bm[j]) * ldb + k0 + bq[j] * 4];
        }

#pragma unroll
        for (int ks = 0; ks < 2; ks++) {
            u32 bhf[4][2], blf[4][2];
#pragma unroll
            for (int ni = 0; ni < 4; ni++) {
                int cb = (ks * 2 + hb) ^ rsb;
                u32 addr = sb32 + 16384 + (rowb + ni * 8) * 64 + cb * 16;
                ldsm_x2(bhf[ni][0], bhf[ni][1], addr);
                ldsm_x2(blf[ni][0], blf[ni][1], addr + 8192);
            }
#pragma unroll
            for (int mi = 0; mi < 4; mi++) {
                int ca = (ks * 2 + ha) ^ rsa;
                u32 addr = sb32 + (rowa + mi * 16) * 64 + ca * 16;
                u32 ah[4], al[4];
                ldsm_x4(ah[0], ah[1], ah[2], ah[3], addr);
                ldsm_x4(al[0], al[1], al[2], al[3], addr + 8192);
#pragma unroll
                for (int ni = 0; ni < 4; ni++) {
                    mma_bf16(acc[mi][ni], ah, bhf[ni]);
                    mma_bf16(acc[mi][ni], ah, blf[ni]);
                    mma_bf16(acc[mi][ni], al, bhf[ni]);
                }
            }
        }
        __syncthreads();
        if (nxt) {
#pragma unroll
            for (int j = 0; j < 2; j++) store_a_pre(an2[j], ac2[j], rah[j], ral[j]);
#pragma unroll
            for (int j = 0; j < 4; j++) store_b_f32(bm[j], bq[j], rbf[j]);
        }
        __syncthreads();
    }

#pragma unroll
    for (int mi = 0; mi < 4; mi++) {
        int mbase = m0 + warp_m * 64 + mi * 16;
#pragma unroll
        for (int ni = 0; ni < 4; ni++) {
            int col = n0 + warp_n * 32 + ni * 8 + tg * 2;
            *(float2*)&C[(long)(mbase + gid) * ldc + col] =
                make_float2(acc[mi][ni][0], acc[mi][ni][1]);
            *(float2*)&C[(long)(mbase + gid + 8) * ldc + col] =
                make_float2(acc[mi][ni][2], acc[mi][ni][3]);
        }
    }
}

// ---------------------------------------------------------------------------
// persistent GRU (R15-proven): tensor-core gh, 384 threads, one-hop barrier.
#define GRU_SMEM2 43008
#define GRU_THREADS 384

__device__ __forceinline__ float sigmf(float x) { return 1.f / (1.f + __expf(-x)); }
__device__ __forceinline__ float tanhfast(float x) { return 2.f / (1.f + __expf(-2.f * x)) - 1.f; }

__global__ __launch_bounds__(GRU_THREADS) void gru_tc(
    const float* __restrict__ GI, const float* __restrict__ h0,
    const float* __restrict__ W_hh, const float* __restrict__ b_hh,
    const __nv_bfloat16* __restrict__ HB0H, const __nv_bfloat16* __restrict__ HB0L,
    __nv_bfloat16* __restrict__ HBH, __nv_bfloat16* __restrict__ HBL)
{
    extern __shared__ char sm8[];
    u32 sb = (u32)__cvta_generic_to_shared(sm8);
    float* ghs = (float*)(sm8 + 32768);
    float* hown = (float*)(sm8 + 40960);

    int tid = threadIdx.x;
    int wid = tid >> 5, lane = tid & 31;
    int jt = blockIdx.x & 15, nt = blockIdx.x >> 4;
    int j0 = jt * 16, n0 = nt * 32;
    int colg = wid % 6, mt = wid / 6;

    unsigned* arr = &g_bar2[nt * 32];

    u32 bhf[16][2], blf[16][2];
    {
        for (int e = tid; e < 3072; e += GRU_THREADS) {
            int r = e >> 6, q = e & 63;
            float4 v = *(const float4*)&W_hh[(long)((r >> 4) * 256 + j0 + (r & 15)) * 256 + q * 4];
            u32 h01, l01, h23, l23;
            cvt_split(v.x, v.y, h01, l01);
            cvt_split(v.z, v.w, h23, l23);
            *(uint2*)(sm8 + r * 512 + (((q >> 1) ^ (r & 7)) * 16) + (q & 1) * 8) =
                make_uint2(h01, h23);
        }
        __syncthreads();
        {
            int rb = colg * 8 + (lane & 7);
            int hb2 = (lane >> 3) & 1;
#pragma unroll
            for (int s = 0; s < 16; s++) {
                u32 addr = sb + rb * 512 + (((s * 2 + hb2) ^ (rb & 7)) * 16);
                ldsm_x2(bhf[s][0], bhf[s][1], addr);
            }
        }
        __syncthreads();
        for (int e = tid; e < 3072; e += GRU_THREADS) {
            int r = e >> 6, q = e & 63;
            float4 v = *(const float4*)&W_hh[(long)((r >> 4) * 256 + j0 + (r & 15)) * 256 + q * 4];
            u32 h01, l01, h23, l23;
            cvt_split(v.x, v.y, h01, l01);
            cvt_split(v.z, v.w, h23, l23);
            *(uint2*)(sm8 + r * 512 + (((q >> 1) ^ (r & 7)) * 16) + (q & 1) * 8) =
                make_uint2(l01, l23);
        }
        __syncthreads();
        {
            int rb = colg * 8 + (lane & 7);
            int hb2 = (lane >> 3) & 1;
#pragma unroll
            for (int s = 0; s < 16; s++) {
                u32 addr = sb + rb * 512 + (((s * 2 + hb2) ^ (rb & 7)) * 16);
                ldsm_x2(blf[s][0], blf[s][1], addr);
            }
        }
        __syncthreads();
    }

    int jj = tid & 15, nb0 = (tid & 255) >> 4;
    float bhr = b_hh[j0 + jj], bhz = b_hh[256 + j0 + jj], bhn = b_hh[512 + j0 + jj];
    if (tid < 256) {
#pragma unroll
        for (int i = 0; i < 2; i++) {
            int n = nb0 + 16 * i;
            hown[n * 16 + jj] = h0[(long)(n0 + n) * H_ + j0 + jj];
        }
    }
    float gr[2], gz[2], gn[2];
    if (tid < 256) {
#pragma unroll
        for (int i = 0; i < 2; i++) {
            long base = ((long)(n0 + nb0 + 16 * i)) * 768 + j0 + jj;
            gr[i] = GI[base]; gz[i] = GI[base + 256]; gn[i] = GI[base + 512];
        }
    }
    __syncthreads();

    for (int t = 0; t < T_; t++) {
        const __nv_bfloat16* srcH = t ? HBH + (long)(t - 1) * N_ * H_ : HB0H;
        const __nv_bfloat16* srcL = t ? HBL + (long)(t - 1) * N_ * H_ : HB0L;
        for (int e = tid; e < 1024; e += GRU_THREADS) {
            int r = e >> 5, c = e & 31;
            u32 soff = r * 512 + ((c ^ (r & 7)) * 16);
            *(uint4*)(sm8 + soff) = *(const uint4*)(srcH + (long)(n0 + r) * 256 + c * 8);
            *(uint4*)(sm8 + 16384 + soff) = *(const uint4*)(srcL + (long)(n0 + r) * 256 + c * 8);
        }
        __syncthreads();

        {
            float acc[4];
#pragma unroll
            for (int v = 0; v < 4; v++) acc[v] = 0.f;
            int rr = mt * 16 + (lane & 15);
            int ha2 = lane >> 4;
#pragma unroll
            for (int s = 0; s < 16; s++) {
                u32 addr = sb + rr * 512 + (((s * 2 + ha2) ^ (rr & 7)) * 16);
                u32 ah[4], al[4];
                ldsm_x4(ah[0], ah[1], ah[2], ah[3], addr);
                ldsm_x4(al[0], al[1], al[2], al[3], addr + 16384);
                mma_bf16(acc, ah, bhf[s]);
                mma_bf16(acc, ah, blf[s]);
                mma_bf16(acc, al, bhf[s]);
            }
            int gid = lane >> 2, tg = lane & 3;
            *(float2*)&ghs[(mt * 16 + gid) * 64 + colg * 8 + tg * 2] =
                make_float2(acc[0], acc[1]);
            *(float2*)&ghs[(mt * 16 + gid + 8) * 64 + colg * 8 + tg * 2] =
                make_float2(acc[2], acc[3]);
        }
        __syncthreads();

        if (tid < 256) {
            __nv_bfloat16* bhd = HBH + (long)t * N_ * H_;
            __nv_bfloat16* bld = HBL + (long)t * N_ * H_;
#pragma unroll
            for (int i = 0; i < 2; i++) {
                int n = nb0 + 16 * i;
                float ghr = ghs[n * 64 + jj];
                float ghz = ghs[n * 64 + 16 + jj];
                float ghn = ghs[n * 64 + 32 + jj];
                float rg = sigmf(gr[i] + ghr + bhr);
                float z  = sigmf(gz[i] + ghz + bhz);
                float nv = tanhfast(gn[i] + rg * (ghn + bhn));
                float hp = hown[n * 16 + jj];
                float hn = (1.f - z) * nv + z * hp;
                hown[n * 16 + jj] = hn;
                long gofs = (long)(n0 + n) * H_ + j0 + jj;
                __nv_bfloat16 hh = __float2bfloat16(hn);
                bhd[gofs] = hh;
                bld[gofs] = __float2bfloat16(hn - __bfloat162float(hh));
            }
        }

        if (t < T_ - 1) {
            __syncthreads();
            if (tid == 0) {
                asm volatile("red.release.gpu.global.add.u32 [%0], %1;"
                             :: "l"(arr), "r"(1u) : "memory");
            }
            if (tid < 256) {
#pragma unroll
                for (int i = 0; i < 2; i++) {
                    long base = ((long)(t + 1) * N_ + n0 + nb0 + 16 * i) * 768 + j0 + jj;
                    gr[i] = GI[base]; gz[i] = GI[base + 256]; gn[i] = GI[base + 512];
                }
            }
            if (tid == 0) {
                unsigned target = (unsigned)(t + 1) * 16u;
                unsigned e;
                do {
                    asm volatile("ld.acquire.gpu.global.u32 %0, [%1];"
                                 : "=r"(e) : "l"(arr) : "memory");
                } while (e < target);
            }
            __syncthreads();
        }
    }
}

// ---------------------------------------------------------------------------
__global__ __launch_bounds__(256) void epilogue_kernel(
    const float* __restrict__ WB, const float* __restrict__ CC,
    const int* __restrict__ actions, const float* __restrict__ Wc,
    const float* __restrict__ bc,
    const __nv_bfloat16* __restrict__ HBH, const __nv_bfloat16* __restrict__ HBL,
    float* __restrict__ out)
{
    int wid = threadIdx.x >> 5, lane = threadIdx.x & 31;
    long idx = (long)blockIdx.x * 8 + wid;
    int t = (int)(idx / N_), n = (int)(idx % N_);
    float cc = CC[idx];
    long base = idx * OUTW_;

    const __nv_bfloat162* hv = (const __nv_bfloat162*)(HBH + idx * 256 + lane * 8);
    const __nv_bfloat162* lv = (const __nv_bfloat162*)(HBL + idx * 256 + lane * 8);
    float h[8];
#pragma unroll
    for (int i = 0; i < 4; i++) {
        float2 fh = __bfloat1622float2(hv[i]);
        float2 fl = __bfloat1622float2(lv[i]);
        h[2 * i] = fh.x + fl.x;
        h[2 * i + 1] = fh.y + fl.y;
    }
    float2* hdst = (float2*)(out + base + 2 + lane * 8);
#pragma unroll
    for (int i = 0; i < 4; i++) hdst[i] = make_float2(h[2 * i], h[2 * i + 1]);

    const float4* wc = (const float4*)Wc;
    float4 c0 = wc[lane * 2], c1 = wc[lane * 2 + 1];
    float d = h[0] * c0.x + h[1] * c0.y + h[2] * c0.z + h[3] * c0.w
            + h[4] * c1.x + h[5] * c1.y + h[6] * c1.z + h[7] * c1.w;
#pragma unroll
    for (int o = 16; o; o >>= 1) d += __shfl_xor_sync(~0u, d, o);

    const float4* wrow = (const float4*)(WB + ((long)n * T_ + t) * L_);
    float4 w0 = wrow[lane * 2], w1 = wrow[lane * 2 + 1];
    float wv[8] = {w0.x * cc, w0.y * cc, w0.z * cc, w0.w * cc,
                   w1.x * cc, w1.y * cc, w1.z * cc, w1.w * cc};
    float mx = wv[0];
#pragma unroll
    for (int i = 1; i < 8; i++) mx = fmaxf(mx, wv[i]);
#pragma unroll
    for (int o = 16; o; o >>= 1) mx = fmaxf(mx, __shfl_xor_sync(~0u, mx, o));
    float e[8], s = 0.f;
#pragma unroll
    for (int i = 0; i < 8; i++) { e[i] = expf(wv[i] - mx); s += e[i]; }
#pragma unroll
    for (int o = 16; o; o >>= 1) s += __shfl_xor_sync(~0u, s, o);
    float inv = 1.f / s;

    int a = actions[idx];
    float2* pdst = (float2*)(out + base + 258 + lane * 8);
    float2* odst = (float2*)(out + base + 514 + lane * 8);
#pragma unroll
    for (int i = 0; i < 4; i++) {
        pdst[i] = make_float2(e[2 * i] * inv, e[2 * i + 1] * inv);
        int l0 = lane * 8 + 2 * i;
        odst[i] = make_float2(l0 == a ? 1.f : 0.f, l0 + 1 == a ? 1.f : 0.f);
    }
    if (lane == 0) {
        out[base + 0] = (float)a;
        out[base + 1] = d + bc[0];
    }
}

// ---------------------------------------------------------------------------
extern "C" void kernel_launch(void* const* d_in, const int* in_sizes, int n_in,
                              void* d_out, int out_size)
{
    const float* cond = (const float*)d_in[0];
    const float* M    = (const float*)d_in[1];
    const float* Km   = (const float*)d_in[2];
    const float* Cm   = (const float*)d_in[3];
    const float* h0   = (const float*)d_in[4];
    const float* p0   = (const float*)d_in[5];
    const float* W0   = (const float*)d_in[6];
    const float* b0   = (const float*)d_in[7];
    const float* W1   = (const float*)d_in[8];
    const float* b1   = (const float*)d_in[9];
    const float* W2   = (const float*)d_in[10];
    const float* b2   = (const float*)d_in[11];
    const float* W_ih = (const float*)d_in[12];
    const float* W_hh = (const float*)d_in[13];
    const float* b_ih = (const float*)d_in[14];
    const float* b_hh = (const float*)d_in[15];
    const float* Wa   = (const float*)d_in[16];
    const float* ba   = (const float*)d_in[17];
    const float* Wc   = (const float*)d_in[18];
    const float* bc   = (const float*)d_in[19];
    const int* actions = (const int*)d_in[20];
    float* out = (float*)d_out;

    float* base = nullptr;
    cudaGetSymbolAddress((void**)&base, g_scratch);
    float* R0 = base + R0_OFF;
    __nv_bfloat16* XAH = (__nv_bfloat16*)(base + XAH_OFF);
    __nv_bfloat16* XAL = (__nv_bfloat16*)(base + XAL_OFF);
    __nv_bfloat16* XBH = (__nv_bfloat16*)(base + XBH_OFF);
    __nv_bfloat16* XBL = (__nv_bfloat16*)(base + XBL_OFF);
    float* GI = base + GI_OFF;
    __nv_bfloat16* KBH = (__nv_bfloat16*)(base + KBH_OFF);
    __nv_bfloat16* KBL = (__nv_bfloat16*)(base + KBL_OFF);
    float* WB = base + WB_OFF;
    float* CC = base + CC_OFF;
    __nv_bfloat16* WT = (__nv_bfloat16*)(base + WT_OFF);
    __nv_bfloat16* HBH = (__nv_bfloat16*)(base + HBH_OFF);
    __nv_bfloat16* HBL = (__nv_bfloat16*)(base + HBL_OFF);
    __nv_bfloat16* HB0H = (__nv_bfloat16*)(base + HB0H_OFF);
    __nv_bfloat16* HB0L = (__nv_bfloat16*)(base + HB0L_OFF);

    void* bar_addr = nullptr;
    cudaGetSymbolAddress(&bar_addr, g_bar2);

    cudaFuncSetAttribute(gru_tc,
                         cudaFuncAttributeMaxDynamicSharedMemorySize, GRU_SMEM2);
    cudaFuncSetAttribute(gemm_v4<true, true, true>,
                         cudaFuncAttributeMaxDynamicSharedMemorySize, GEMM3_SMEM);
    cudaFuncSetAttribute(gemm_v4<true, true, false>,
                         cudaFuncAttributeMaxDynamicSharedMemorySize, GEMM3_SMEM);
    cudaFuncSetAttribute(gemm_v4<false, false, false>,
                         cudaFuncAttributeMaxDynamicSharedMemorySize, GEMM3_SMEM);
    cudaFuncSetAttribute(gemm_v4<false, true, false>,
                         cudaFuncAttributeMaxDynamicSharedMemorySize, GEMM3_SMEM);

    // phase 0: weight/h0 conversion + t0 + CC
    convert_wall<<<2112, 256>>>(W0, W1, W2, W_ih, Wa, h0, WT, HB0H, HB0L);
    t0_kernel<<<N_, 256>>>(p0, M, Cm, R0, CC);
    cc_kernel<<<(ROWS_ - N_) / 256, 256>>>(Cm, actions, CC);

    // phase A (G0 gathers A inline from cond/M/R0/actions)
    gemm_v4<true, true, true><<<dim3(ROWS_ / 128, 2), 256, GEMM3_SMEM>>>(
        nullptr, nullptr, cond, M, R0, actions,
        WT + W0H, WT + W0L, b0, nullptr, XAH, XAL, 320, 320, 256);
    gemm_v4<true, true, false><<<dim3(ROWS_ / 128, 2), 256, GEMM3_SMEM>>>(
        XAH, XAL, nullptr, nullptr, nullptr, nullptr,
        WT + W1H, WT + W1L, b1, nullptr, XBH, XBL, 256, 256, 256);
    gemm_v4<true, true, false><<<dim3(ROWS_ / 128, 2), 256, GEMM3_SMEM>>>(
        XBH, XBL, nullptr, nullptr, nullptr, nullptr,
        WT + W2H, WT + W2L, b2, nullptr, XAH, XAL, 256, 256, 256);
    gemm_v4<false, false, false><<<dim3(ROWS_ / 128, 6), 256, GEMM3_SMEM>>>(
        XAH, XAL, nullptr, nullptr, nullptr, nullptr,
        WT + WIHH, WT + WIHL, b_ih, GI, nullptr, nullptr, 256, 256, 768);

    // phase B: persistent tensor-core GRU
    cudaMemsetAsync(bar_addr, 0, 8 * 32 * sizeof(unsigned));
    gru_tc<<<128, GRU_THREADS, GRU_SMEM2>>>(GI, h0, W_hh, b_hh, HB0H, HB0L, HBH, HBL);

    // phase C
    gemm_v4<false, true, false><<<dim3(ROWS_ / 128, 2), 256, GEMM3_SMEM>>>(
        HBH, HBL, nullptr, nullptr, nullptr, nullptr,
        WT + WAH, WT + WAL, ba, nullptr, KBH, KBL, 256, 256, 256);
    gemm_km<<<dim3(1, 2, 256), 256, BGEMM_SMEM>>>(
        KBH, KBL, Km, WB, 256, 256, 256, 256,
        (long)T_ * 256, (long)L_ * H_, (long)T_ * L_);
    epilogue_kernel<<<ROWS_ / 8, 256>>>(WB, CC, actions, Wc, bc, HBH, HBL, out);
}